// round 13
// baseline (speedup 1.0000x reference)
#include <cuda_runtime.h>
#include <cstdint>

#define NN 100000
#define EE 1600000
#define EA 7
#define HH 64
#define LL 32
#define GG 512
#define CC 6

// ---------------- scratch (static device globals: no allocation) -------------
__device__ float g_agg1[NN];
__device__ float g_h1[(size_t)NN * HH];
__device__ float g_agg2[(size_t)NN * HH];
__device__ float g_zsum[GG * LL];
__device__ float g_cnt[GG];

// ---------------- f32x2 / vector-red helpers ---------------------------------
typedef unsigned long long u64;
__device__ __forceinline__ u64 pack2f(float x, float y) {
    u64 r; asm("mov.b64 %0,{%1,%2};" : "=l"(r) : "f"(x), "f"(y)); return r;
}
__device__ __forceinline__ u64 pack2(float x) {
    u64 r; asm("mov.b64 %0,{%1,%1};" : "=l"(r) : "f"(x)); return r;
}
__device__ __forceinline__ float2 unpack2(u64 v) {
    float2 f; asm("mov.b64 {%0,%1},%2;" : "=f"(f.x), "=f"(f.y) : "l"(v)); return f;
}
__device__ __forceinline__ u64 fma2(u64 a, u64 b, u64 c) {
    u64 d; asm("fma.rn.f32x2 %0,%1,%2,%3;" : "=l"(d) : "l"(a), "l"(b), "l"(c)); return d;
}
__device__ __forceinline__ void red2(float* p, float2 v) {
    asm volatile("red.global.add.v2.f32 [%0],{%1,%2};"
                 :: "l"(p), "f"(v.x), "f"(v.y) : "memory");
}

// ---------------- JAX threefry2x32-20 (partitionable) + normal ----------------
__device__ __forceinline__ void tf_round(uint32_t& x0, uint32_t& x1, int r) {
    x0 += x1;
    x1 = (x1 << r) | (x1 >> (32 - r));
    x1 ^= x0;
}
__device__ __forceinline__ void threefry2x32(uint32_t k0, uint32_t k1,
                                             uint32_t c0, uint32_t c1,
                                             uint32_t& o0, uint32_t& o1) {
    uint32_t ks2 = k0 ^ k1 ^ 0x1BD11BDAu;
    uint32_t x0 = c0 + k0, x1 = c1 + k1;
    tf_round(x0,x1,13); tf_round(x0,x1,15); tf_round(x0,x1,26); tf_round(x0,x1,6);
    x0 += k1;  x1 += ks2 + 1u;
    tf_round(x0,x1,17); tf_round(x0,x1,29); tf_round(x0,x1,16); tf_round(x0,x1,24);
    x0 += ks2; x1 += k0 + 2u;
    tf_round(x0,x1,13); tf_round(x0,x1,15); tf_round(x0,x1,26); tf_round(x0,x1,6);
    x0 += k0;  x1 += k1 + 3u;
    tf_round(x0,x1,17); tf_round(x0,x1,29); tf_round(x0,x1,16); tf_round(x0,x1,24);
    x0 += k1;  x1 += ks2 + 4u;
    tf_round(x0,x1,13); tf_round(x0,x1,15); tf_round(x0,x1,26); tf_round(x0,x1,6);
    x0 += ks2; x1 += k0 + 5u;
    o0 = x0; o1 = x1;
}
__device__ __forceinline__ float jax_normal_42(uint32_t flat) {
    uint32_t o0, o1;
    threefry2x32(0u, 42u, 0u, flat, o0, o1);
    uint32_t bits = o0 ^ o1;
    float f = __uint_as_float((bits >> 9) | 0x3F800000u) - 1.0f;   // [0,1)
    const float lo = -0.99999994f;
    float u = fmaf(f, 1.0f - lo, lo);
    u = fmaxf(u, lo);
    return 1.41421356f * erfinvf(u);
}

// ---------------- kernels ----------------------------------------------------

// zero agg1 + zsum + cnt (agg2 zeroed inside k_mlp1)
__global__ __launch_bounds__(256) void k_zero() {            // grid 98
    int i = blockIdx.x * 256 + threadIdx.x;
    float4 z = make_float4(0.f, 0.f, 0.f, 0.f);
    if (i < NN / 4)      ((float4*)g_agg1)[i] = z;
    if (i < GG * LL / 4) ((float4*)g_zsum)[i] = z;
    if (i < GG / 4)      ((float4*)g_cnt)[i]  = z;
}

// edge pass 1 (scalar features); eattr staged via smem. 256 edges/block.
__global__ __launch_bounds__(256) void k_edge1(const float* __restrict__ x,
                                               const int*   __restrict__ ei,
                                               const float* __restrict__ eattr,
                                               const float* __restrict__ We1,
                                               const float* __restrict__ be1) {
    __shared__ float sea[256 * EA];
    int tid = threadIdx.x;
    size_t base = (size_t)blockIdx.x * 256;
    for (int i = tid; i < 256 * EA; i += 256) sea[i] = eattr[base * EA + i];
    float rW[EA];
#pragma unroll
    for (int a = 0; a < EA; a++) rW[a] = __ldg(We1 + a);
    float rbe = __ldg(be1);
    __syncthreads();
    size_t e = base + tid;
    int s = ei[e], d = ei[EE + e];
    float v = rbe;
#pragma unroll
    for (int a = 0; a < EA; a++) v = fmaf(sea[tid * EA + a], rW[a], v);
    float m = fmaxf(x[s] + v, 0.f);
    atomicAdd(&g_agg1[d], m);
}

// node MLP 1: 16 thr/node-group, 5 nodes per group, 80 nodes/block (grid 1250).
// Also zeroes g_agg2 for its nodes (before k_edge2 runs).
__global__ __launch_bounds__(256) void k_mlp1(const float* __restrict__ x,
                                              const float* __restrict__ W11,
                                              const float* __restrict__ b11,
                                              const float* __restrict__ W12,
                                              const float* __restrict__ b12,
                                              const float* __restrict__ eps1) {
    __shared__ float sh[16][5][68];
    int tid = threadIdx.x;
    int q = tid & 15, nl = tid >> 4;
    int base = blockIdx.x * 80 + nl * 5;
    float epsv = 1.0f + __ldg(eps1);
    float4 w11 = __ldg((const float4*)(W11 + q * 4));
    float4 b1v = __ldg((const float4*)(b11 + q * 4));
    const float4 zf4 = make_float4(0.f, 0.f, 0.f, 0.f);
#pragma unroll
    for (int n = 0; n < 5; n++) {
        int node = base + n;
        size_t off = (size_t)node * HH + q * 4;
        *(float4*)(g_agg2 + off) = zf4;
        float hx = fmaf(epsv, __ldg(x + node), g_agg1[node]);
        float4 t;
        t.x = fmaxf(fmaf(hx, w11.x, b1v.x), 0.f);
        t.y = fmaxf(fmaf(hx, w11.y, b1v.y), 0.f);
        t.z = fmaxf(fmaf(hx, w11.z, b1v.z), 0.f);
        t.w = fmaxf(fmaf(hx, w11.w, b1v.w), 0.f);
        *(float4*)&sh[nl][n][q * 4] = t;
    }
    __syncwarp();
    float4 b2v = __ldg((const float4*)(b12 + q * 4));
    u64 a0[5], a1[5];
#pragma unroll
    for (int n = 0; n < 5; n++) { a0[n] = pack2f(b2v.x, b2v.y); a1[n] = pack2f(b2v.z, b2v.w); }
#pragma unroll
    for (int j4 = 0; j4 < 16; j4++) {
        float4 w0 = __ldg((const float4*)(W12 + (j4 * 4 + 0) * HH + q * 4));
        float4 w1 = __ldg((const float4*)(W12 + (j4 * 4 + 1) * HH + q * 4));
        float4 w2 = __ldg((const float4*)(W12 + (j4 * 4 + 2) * HH + q * 4));
        float4 w3 = __ldg((const float4*)(W12 + (j4 * 4 + 3) * HH + q * 4));
#pragma unroll
        for (int n = 0; n < 5; n++) {
            float4 hv = *(const float4*)&sh[nl][n][j4 * 4];
            a0[n] = fma2(pack2f(w0.x, w0.y), pack2(hv.x), a0[n]);
            a1[n] = fma2(pack2f(w0.z, w0.w), pack2(hv.x), a1[n]);
            a0[n] = fma2(pack2f(w1.x, w1.y), pack2(hv.y), a0[n]);
            a1[n] = fma2(pack2f(w1.z, w1.w), pack2(hv.y), a1[n]);
            a0[n] = fma2(pack2f(w2.x, w2.y), pack2(hv.z), a0[n]);
            a1[n] = fma2(pack2f(w2.z, w2.w), pack2(hv.z), a1[n]);
            a0[n] = fma2(pack2f(w3.x, w3.y), pack2(hv.w), a0[n]);
            a1[n] = fma2(pack2f(w3.z, w3.w), pack2(hv.w), a1[n]);
        }
    }
#pragma unroll
    for (int n = 0; n < 5; n++) {
        float2 lo = unpack2(a0[n]), hi = unpack2(a1[n]);
        float4 o;
        o.x = fmaxf(lo.x, 0.f); o.y = fmaxf(lo.y, 0.f);
        o.z = fmaxf(hi.x, 0.f); o.w = fmaxf(hi.y, 0.f);
        *(float4*)(g_h1 + (size_t)(base + n) * HH + q * 4) = o;
    }
}

// edge pass 2: 128 edges/block (grid 12500), 32 thr/edge (1 warp = 1 edge/iter),
// float2 lanes, sea padded to stride-8 for 2x LDS.128 broadcast, red.v2.
__global__ __launch_bounds__(256, 5) void k_edge2(const int*   __restrict__ ei,
                                                  const float* __restrict__ eattr,
                                                  const float* __restrict__ We2,
                                                  const float* __restrict__ be2) {
    __shared__ float sea[128 * 8];
    __shared__ int   ss[128], sd[128];
    int tid = threadIdx.x;
    size_t base = (size_t)blockIdx.x * 128;
    for (int i = tid; i < 128 * EA; i += 256) {
        int e = i / EA, a = i - e * EA;
        sea[e * 8 + a] = eattr[base * EA + i];
    }
    if (tid < 128)       ss[tid] = ei[base + tid];
    else                 sd[tid - 128] = ei[EE + base + (tid - 128)];
    int q = tid & 31, el = tid >> 5;                     // lane owns dims 2q,2q+1
    u64 rw[EA];
#pragma unroll
    for (int a = 0; a < EA; a++) rw[a] = __ldg((const u64*)(We2 + a * HH + q * 2));
    u64 rb = __ldg((const u64*)(be2 + q * 2));
    __syncthreads();
#pragma unroll 4
    for (int it = 0; it < 16; it++) {
        int e = it * 8 + el;
        int s = ss[e], d = sd[e];
        float2 h = __ldg((const float2*)(g_h1 + (size_t)s * HH + q * 2));
        float4 ea0 = *(const float4*)&sea[e * 8];
        float4 ea1 = *(const float4*)&sea[e * 8 + 4];    // .w unused padding
        u64 v = rb;
        v = fma2(rw[0], pack2(ea0.x), v);
        v = fma2(rw[1], pack2(ea0.y), v);
        v = fma2(rw[2], pack2(ea0.z), v);
        v = fma2(rw[3], pack2(ea0.w), v);
        v = fma2(rw[4], pack2(ea1.x), v);
        v = fma2(rw[5], pack2(ea1.y), v);
        v = fma2(rw[6], pack2(ea1.z), v);
        float2 vf = unpack2(v);
        float2 m = make_float2(fmaxf(h.x + vf.x, 0.f), fmaxf(h.y + vf.y, 0.f));
        red2(g_agg2 + (size_t)d * HH + q * 2, m);
    }
}

// FUSED node MLP 2 + heads: 16 thr/group, 5 nodes/group, 80 nodes/block.
// h2 lives only in SMEM. Thread q owns output dims 4q..4q+3 (mlp) / 2q,2q+1 (latent).
__global__ __launch_bounds__(256) void k_mlp2h(const float* __restrict__ W21,
                                               const float* __restrict__ b21,
                                               const float* __restrict__ W22,
                                               const float* __restrict__ b22,
                                               const float* __restrict__ eps2,
                                               const float* __restrict__ Wmu,
                                               const float* __restrict__ bmu,
                                               const float* __restrict__ Wlv,
                                               const float* __restrict__ blv,
                                               const int*   __restrict__ batch,
                                               float* __restrict__ out) {
    __shared__ float sh[16][5][68];
    int tid = threadIdx.x;
    int q = tid & 15, nl = tid >> 4;
    int base = blockIdx.x * 80 + nl * 5;
    float epsv = 1.0f + __ldg(eps2);
    // stage h_in = (1+eps)*h1 + agg2
#pragma unroll
    for (int n = 0; n < 5; n++) {
        size_t off = (size_t)(base + n) * HH + q * 4;
        float4 h1v = __ldg((const float4*)(g_h1 + off));
        float4 ag  = *(const float4*)(g_agg2 + off);
        float4 hin;
        hin.x = fmaf(epsv, h1v.x, ag.x);
        hin.y = fmaf(epsv, h1v.y, ag.y);
        hin.z = fmaf(epsv, h1v.z, ag.z);
        hin.w = fmaf(epsv, h1v.w, ag.w);
        *(float4*)&sh[nl][n][q * 4] = hin;
    }
    __syncwarp();
    u64 a0[5], a1[5];
    // ---- MLP layer 1 ----
    {
        float4 bv = __ldg((const float4*)(b21 + q * 4));
#pragma unroll
        for (int n = 0; n < 5; n++) { a0[n] = pack2f(bv.x, bv.y); a1[n] = pack2f(bv.z, bv.w); }
#pragma unroll
        for (int j4 = 0; j4 < 16; j4++) {
            float4 w0 = __ldg((const float4*)(W21 + (j4 * 4 + 0) * HH + q * 4));
            float4 w1 = __ldg((const float4*)(W21 + (j4 * 4 + 1) * HH + q * 4));
            float4 w2 = __ldg((const float4*)(W21 + (j4 * 4 + 2) * HH + q * 4));
            float4 w3 = __ldg((const float4*)(W21 + (j4 * 4 + 3) * HH + q * 4));
#pragma unroll
            for (int n = 0; n < 5; n++) {
                float4 hv = *(const float4*)&sh[nl][n][j4 * 4];
                a0[n] = fma2(pack2f(w0.x, w0.y), pack2(hv.x), a0[n]);
                a1[n] = fma2(pack2f(w0.z, w0.w), pack2(hv.x), a1[n]);
                a0[n] = fma2(pack2f(w1.x, w1.y), pack2(hv.y), a0[n]);
                a1[n] = fma2(pack2f(w1.z, w1.w), pack2(hv.y), a1[n]);
                a0[n] = fma2(pack2f(w2.x, w2.y), pack2(hv.z), a0[n]);
                a1[n] = fma2(pack2f(w2.z, w2.w), pack2(hv.z), a1[n]);
                a0[n] = fma2(pack2f(w3.x, w3.y), pack2(hv.w), a0[n]);
                a1[n] = fma2(pack2f(w3.z, w3.w), pack2(hv.w), a1[n]);
            }
        }
        __syncwarp();
#pragma unroll
        for (int n = 0; n < 5; n++) {
            float2 lo = unpack2(a0[n]), hi = unpack2(a1[n]);
            float4 t;
            t.x = fmaxf(lo.x, 0.f); t.y = fmaxf(lo.y, 0.f);
            t.z = fmaxf(hi.x, 0.f); t.w = fmaxf(hi.y, 0.f);
            *(float4*)&sh[nl][n][q * 4] = t;
        }
        __syncwarp();
    }
    // ---- MLP layer 2 (h2 -> smem) ----
    {
        float4 bv = __ldg((const float4*)(b22 + q * 4));
#pragma unroll
        for (int n = 0; n < 5; n++) { a0[n] = pack2f(bv.x, bv.y); a1[n] = pack2f(bv.z, bv.w); }
#pragma unroll
        for (int j4 = 0; j4 < 16; j4++) {
            float4 w0 = __ldg((const float4*)(W22 + (j4 * 4 + 0) * HH + q * 4));
            float4 w1 = __ldg((const float4*)(W22 + (j4 * 4 + 1) * HH + q * 4));
            float4 w2 = __ldg((const float4*)(W22 + (j4 * 4 + 2) * HH + q * 4));
            float4 w3 = __ldg((const float4*)(W22 + (j4 * 4 + 3) * HH + q * 4));
#pragma unroll
            for (int n = 0; n < 5; n++) {
                float4 hv = *(const float4*)&sh[nl][n][j4 * 4];
                a0[n] = fma2(pack2f(w0.x, w0.y), pack2(hv.x), a0[n]);
                a1[n] = fma2(pack2f(w0.z, w0.w), pack2(hv.x), a1[n]);
                a0[n] = fma2(pack2f(w1.x, w1.y), pack2(hv.y), a0[n]);
                a1[n] = fma2(pack2f(w1.z, w1.w), pack2(hv.y), a1[n]);
                a0[n] = fma2(pack2f(w2.x, w2.y), pack2(hv.z), a0[n]);
                a1[n] = fma2(pack2f(w2.z, w2.w), pack2(hv.z), a1[n]);
                a0[n] = fma2(pack2f(w3.x, w3.y), pack2(hv.w), a0[n]);
                a1[n] = fma2(pack2f(w3.z, w3.w), pack2(hv.w), a1[n]);
            }
        }
        __syncwarp();
#pragma unroll
        for (int n = 0; n < 5; n++) {
            float2 lo = unpack2(a0[n]), hi = unpack2(a1[n]);
            float4 o;
            o.x = fmaxf(lo.x, 0.f); o.y = fmaxf(lo.y, 0.f);
            o.z = fmaxf(hi.x, 0.f); o.w = fmaxf(hi.y, 0.f);
            *(float4*)&sh[nl][n][q * 4] = o;
        }
        __syncwarp();
    }
    // ---- heads: mu/lv/z + pooled sums ----
    int l0 = q * 2;
    u64 amu[5], alv[5];
    u64 bm = __ldg((const u64*)(bmu + l0));
    u64 bl = __ldg((const u64*)(blv + l0));
#pragma unroll
    for (int n = 0; n < 5; n++) { amu[n] = bm; alv[n] = bl; }
#pragma unroll
    for (int j4 = 0; j4 < 16; j4++) {
        u64 wm0 = __ldg((const u64*)(Wmu + (j4 * 4 + 0) * LL + l0));
        u64 wm1 = __ldg((const u64*)(Wmu + (j4 * 4 + 1) * LL + l0));
        u64 wm2 = __ldg((const u64*)(Wmu + (j4 * 4 + 2) * LL + l0));
        u64 wm3 = __ldg((const u64*)(Wmu + (j4 * 4 + 3) * LL + l0));
        u64 wl0 = __ldg((const u64*)(Wlv + (j4 * 4 + 0) * LL + l0));
        u64 wl1 = __ldg((const u64*)(Wlv + (j4 * 4 + 1) * LL + l0));
        u64 wl2 = __ldg((const u64*)(Wlv + (j4 * 4 + 2) * LL + l0));
        u64 wl3 = __ldg((const u64*)(Wlv + (j4 * 4 + 3) * LL + l0));
#pragma unroll
        for (int n = 0; n < 5; n++) {
            float4 hv = *(const float4*)&sh[nl][n][j4 * 4];
            u64 h0 = pack2(hv.x), h1 = pack2(hv.y), h2 = pack2(hv.z), h3 = pack2(hv.w);
            amu[n] = fma2(wm0, h0, amu[n]);
            alv[n] = fma2(wl0, h0, alv[n]);
            amu[n] = fma2(wm1, h1, amu[n]);
            alv[n] = fma2(wl1, h1, alv[n]);
            amu[n] = fma2(wm2, h2, amu[n]);
            alv[n] = fma2(wl2, h2, alv[n]);
            amu[n] = fma2(wm3, h3, amu[n]);
            alv[n] = fma2(wl3, h3, alv[n]);
        }
    }
    float* out_z  = out;
    float* out_mu = out + (size_t)NN * LL;
    float* out_lv = out + (size_t)2 * NN * LL;
    float2 accz = make_float2(0.f, 0.f);
    float accn = 0.f;
    int accb = -1;
#pragma unroll
    for (int n = 0; n < 5; n++) {
        int node = base + n;
        float2 mu = unpack2(amu[n]), lv = unpack2(alv[n]);
        uint32_t flat = (uint32_t)node * LL + (uint32_t)l0;
        float nz0 = jax_normal_42(flat);
        float nz1 = jax_normal_42(flat + 1u);
        float2 z;
        z.x = fmaf(nz0, expf(0.5f * lv.x), mu.x);
        z.y = fmaf(nz1, expf(0.5f * lv.y), mu.y);
        *(float2*)(out_z  + flat) = z;
        *(float2*)(out_mu + flat) = mu;
        *(float2*)(out_lv + flat) = lv;
        int b = __ldg(batch + node);
        if (b != accb) {
            if (accb >= 0) {
                red2(g_zsum + accb * LL + l0, accz);
                if (q == 0) atomicAdd(&g_cnt[accb], accn);
            }
            accb = b; accz = z; accn = 1.f;
        } else {
            accz.x += z.x; accz.y += z.y; accn += 1.f;
        }
    }
    if (accb >= 0) {
        red2(g_zsum + accb * LL + l0, accz);
        if (q == 0) atomicAdd(&g_cnt[accb], accn);
    }
}

__global__ __launch_bounds__(256) void k_logits(const float* __restrict__ Wc,
                                                const float* __restrict__ bc,
                                                float* __restrict__ out) {
    int g = blockIdx.x * 256 + threadIdx.x;
    if (g >= GG) return;
    float inv = 1.0f / fmaxf(g_cnt[g], 1.0f);
    float acc[CC];
#pragma unroll
    for (int c = 0; c < CC; c++) acc[c] = __ldg(bc + c);
#pragma unroll
    for (int l = 0; l < LL; l++) {
        float v = g_zsum[g * LL + l] * inv;
#pragma unroll
        for (int c = 0; c < CC; c++) acc[c] = fmaf(v, __ldg(Wc + l * CC + c), acc[c]);
    }
    float* out_lg = out + (size_t)3 * NN * LL;
#pragma unroll
    for (int c = 0; c < CC; c++) out_lg[(size_t)g * CC + c] = acc[c];
}

// ---------------- launch -----------------------------------------------------
extern "C" void kernel_launch(void* const* d_in, const int* in_sizes, int n_in,
                              void* d_out, int out_size) {
    const float* x     = (const float*)d_in[0];
    const int*   ei    = (const int*)  d_in[1];
    const float* eattr = (const float*)d_in[2];
    const int*   batch = (const int*)  d_in[3];
    const float* We1  = (const float*)d_in[4];
    const float* be1  = (const float*)d_in[5];
    const float* W11  = (const float*)d_in[6];
    const float* b11  = (const float*)d_in[7];
    const float* W12  = (const float*)d_in[8];
    const float* b12  = (const float*)d_in[9];
    const float* eps1 = (const float*)d_in[10];
    const float* We2  = (const float*)d_in[11];
    const float* be2  = (const float*)d_in[12];
    const float* W21  = (const float*)d_in[13];
    const float* b21  = (const float*)d_in[14];
    const float* W22  = (const float*)d_in[15];
    const float* b22  = (const float*)d_in[16];
    const float* eps2 = (const float*)d_in[17];
    const float* Wmu  = (const float*)d_in[18];
    const float* bmu  = (const float*)d_in[19];
    const float* Wlv  = (const float*)d_in[20];
    const float* blv  = (const float*)d_in[21];
    const float* Wc   = (const float*)d_in[22];
    const float* bc   = (const float*)d_in[23];
    float* out = (float*)d_out;

    k_zero  <<<98, 256>>>();
    k_edge1 <<<EE / 256, 256>>>(x, ei, eattr, We1, be1);
    k_mlp1  <<<NN / 80, 256>>>(x, W11, b11, W12, b12, eps1);
    k_edge2 <<<EE / 128, 256>>>(ei, eattr, We2, be2);
    k_mlp2h <<<NN / 80, 256>>>(W21, b21, W22, b22, eps2,
                               Wmu, bmu, Wlv, blv, batch, out);
    k_logits<<<2, 256>>>(Wc, bc, out);
}

// round 14
// speedup vs baseline: 1.4018x; 1.4018x over previous
#include <cuda_runtime.h>
#include <cstdint>

#define NN 100000
#define EE 1600000
#define EA 7
#define HH 64
#define LL 32
#define GG 512
#define CC 6

// ---------------- scratch (static device globals: no allocation) -------------
__device__ float g_agg1[NN];
__device__ float g_h1[(size_t)NN * HH];
__device__ float g_agg2[(size_t)NN * HH];
__device__ float g_h2[(size_t)NN * HH];
__device__ float g_zsum[GG * LL];
__device__ float g_cnt[GG];

// ---------------- f32x2 / vector-red helpers ---------------------------------
typedef unsigned long long u64;
__device__ __forceinline__ u64 pack2f(float x, float y) {
    u64 r; asm("mov.b64 %0,{%1,%2};" : "=l"(r) : "f"(x), "f"(y)); return r;
}
__device__ __forceinline__ u64 pack2(float x) {
    u64 r; asm("mov.b64 %0,{%1,%1};" : "=l"(r) : "f"(x)); return r;
}
__device__ __forceinline__ float2 unpack2(u64 v) {
    float2 f; asm("mov.b64 {%0,%1},%2;" : "=f"(f.x), "=f"(f.y) : "l"(v)); return f;
}
__device__ __forceinline__ u64 fma2(u64 a, u64 b, u64 c) {
    u64 d; asm("fma.rn.f32x2 %0,%1,%2,%3;" : "=l"(d) : "l"(a), "l"(b), "l"(c)); return d;
}
__device__ __forceinline__ void red4(float* p, float4 v) {
    asm volatile("red.global.add.v4.f32 [%0],{%1,%2,%3,%4};"
                 :: "l"(p), "f"(v.x), "f"(v.y), "f"(v.z), "f"(v.w) : "memory");
}
__device__ __forceinline__ void red2(float* p, float2 v) {
    asm volatile("red.global.add.v2.f32 [%0],{%1,%2};"
                 :: "l"(p), "f"(v.x), "f"(v.y) : "memory");
}

// ---------------- JAX threefry2x32-20 (partitionable) + normal ----------------
__device__ __forceinline__ void tf_round(uint32_t& x0, uint32_t& x1, int r) {
    x0 += x1;
    x1 = (x1 << r) | (x1 >> (32 - r));
    x1 ^= x0;
}
__device__ __forceinline__ void threefry2x32(uint32_t k0, uint32_t k1,
                                             uint32_t c0, uint32_t c1,
                                             uint32_t& o0, uint32_t& o1) {
    uint32_t ks2 = k0 ^ k1 ^ 0x1BD11BDAu;
    uint32_t x0 = c0 + k0, x1 = c1 + k1;
    tf_round(x0,x1,13); tf_round(x0,x1,15); tf_round(x0,x1,26); tf_round(x0,x1,6);
    x0 += k1;  x1 += ks2 + 1u;
    tf_round(x0,x1,17); tf_round(x0,x1,29); tf_round(x0,x1,16); tf_round(x0,x1,24);
    x0 += ks2; x1 += k0 + 2u;
    tf_round(x0,x1,13); tf_round(x0,x1,15); tf_round(x0,x1,26); tf_round(x0,x1,6);
    x0 += k0;  x1 += k1 + 3u;
    tf_round(x0,x1,17); tf_round(x0,x1,29); tf_round(x0,x1,16); tf_round(x0,x1,24);
    x0 += k1;  x1 += ks2 + 4u;
    tf_round(x0,x1,13); tf_round(x0,x1,15); tf_round(x0,x1,26); tf_round(x0,x1,6);
    x0 += ks2; x1 += k0 + 5u;
    o0 = x0; o1 = x1;
}
__device__ __forceinline__ float jax_normal_42(uint32_t flat) {
    uint32_t o0, o1;
    threefry2x32(0u, 42u, 0u, flat, o0, o1);
    uint32_t bits = o0 ^ o1;
    float f = __uint_as_float((bits >> 9) | 0x3F800000u) - 1.0f;   // [0,1)
    const float lo = -0.99999994f;
    float u = fmaf(f, 1.0f - lo, lo);
    u = fmaxf(u, lo);
    return 1.41421356f * erfinvf(u);
}

// ---------------- kernels ----------------------------------------------------

// zero agg1 + zsum + cnt (agg2 zeroed inside k_mlp1)
__global__ __launch_bounds__(256) void k_zero() {            // grid 98
    int i = blockIdx.x * 256 + threadIdx.x;
    float4 z = make_float4(0.f, 0.f, 0.f, 0.f);
    if (i < NN / 4)      ((float4*)g_agg1)[i] = z;
    if (i < GG * LL / 4) ((float4*)g_zsum)[i] = z;
    if (i < GG / 4)      ((float4*)g_cnt)[i]  = z;
}

// edge pass 1 (scalar features); eattr staged via smem. 256 edges/block.
__global__ __launch_bounds__(256) void k_edge1(const float* __restrict__ x,
                                               const int*   __restrict__ ei,
                                               const float* __restrict__ eattr,
                                               const float* __restrict__ We1,
                                               const float* __restrict__ be1) {
    __shared__ float sea[256 * EA];
    int tid = threadIdx.x;
    size_t base = (size_t)blockIdx.x * 256;
    for (int i = tid; i < 256 * EA; i += 256) sea[i] = eattr[base * EA + i];
    float rW[EA];
#pragma unroll
    for (int a = 0; a < EA; a++) rW[a] = __ldg(We1 + a);
    float rbe = __ldg(be1);
    __syncthreads();
    size_t e = base + tid;
    int s = ei[e], d = ei[EE + e];
    float v = rbe;
#pragma unroll
    for (int a = 0; a < EA; a++) v = fmaf(sea[tid * EA + a], rW[a], v);
    float m = fmaxf(x[s] + v, 0.f);
    atomicAdd(&g_agg1[d], m);
}

// node MLP 1: 16 thr/node-group, 5 nodes per group, 80 nodes/block (grid 1250).
// Also zeroes g_agg2 for its nodes (before k_edge2 runs).
__global__ __launch_bounds__(256) void k_mlp1(const float* __restrict__ x,
                                              const float* __restrict__ W11,
                                              const float* __restrict__ b11,
                                              const float* __restrict__ W12,
                                              const float* __restrict__ b12,
                                              const float* __restrict__ eps1) {
    __shared__ float sh[16][5][68];
    int tid = threadIdx.x;
    int q = tid & 15, nl = tid >> 4;
    int base = blockIdx.x * 80 + nl * 5;
    float epsv = 1.0f + __ldg(eps1);
    float4 w11 = __ldg((const float4*)(W11 + q * 4));
    float4 b1v = __ldg((const float4*)(b11 + q * 4));
    const float4 zf4 = make_float4(0.f, 0.f, 0.f, 0.f);
#pragma unroll
    for (int n = 0; n < 5; n++) {
        int node = base + n;
        size_t off = (size_t)node * HH + q * 4;
        *(float4*)(g_agg2 + off) = zf4;
        float hx = fmaf(epsv, __ldg(x + node), g_agg1[node]);
        float4 t;
        t.x = fmaxf(fmaf(hx, w11.x, b1v.x), 0.f);
        t.y = fmaxf(fmaf(hx, w11.y, b1v.y), 0.f);
        t.z = fmaxf(fmaf(hx, w11.z, b1v.z), 0.f);
        t.w = fmaxf(fmaf(hx, w11.w, b1v.w), 0.f);
        *(float4*)&sh[nl][n][q * 4] = t;
    }
    __syncwarp();
    float4 b2v = __ldg((const float4*)(b12 + q * 4));
    u64 a0[5], a1[5];
#pragma unroll
    for (int n = 0; n < 5; n++) { a0[n] = pack2f(b2v.x, b2v.y); a1[n] = pack2f(b2v.z, b2v.w); }
#pragma unroll
    for (int j4 = 0; j4 < 16; j4++) {
        float4 w0 = __ldg((const float4*)(W12 + (j4 * 4 + 0) * HH + q * 4));
        float4 w1 = __ldg((const float4*)(W12 + (j4 * 4 + 1) * HH + q * 4));
        float4 w2 = __ldg((const float4*)(W12 + (j4 * 4 + 2) * HH + q * 4));
        float4 w3 = __ldg((const float4*)(W12 + (j4 * 4 + 3) * HH + q * 4));
#pragma unroll
        for (int n = 0; n < 5; n++) {
            float4 hv = *(const float4*)&sh[nl][n][j4 * 4];
            a0[n] = fma2(pack2f(w0.x, w0.y), pack2(hv.x), a0[n]);
            a1[n] = fma2(pack2f(w0.z, w0.w), pack2(hv.x), a1[n]);
            a0[n] = fma2(pack2f(w1.x, w1.y), pack2(hv.y), a0[n]);
            a1[n] = fma2(pack2f(w1.z, w1.w), pack2(hv.y), a1[n]);
            a0[n] = fma2(pack2f(w2.x, w2.y), pack2(hv.z), a0[n]);
            a1[n] = fma2(pack2f(w2.z, w2.w), pack2(hv.z), a1[n]);
            a0[n] = fma2(pack2f(w3.x, w3.y), pack2(hv.w), a0[n]);
            a1[n] = fma2(pack2f(w3.z, w3.w), pack2(hv.w), a1[n]);
        }
    }
#pragma unroll
    for (int n = 0; n < 5; n++) {
        float2 lo = unpack2(a0[n]), hi = unpack2(a1[n]);
        float4 o;
        o.x = fmaxf(lo.x, 0.f); o.y = fmaxf(lo.y, 0.f);
        o.z = fmaxf(hi.x, 0.f); o.w = fmaxf(hi.y, 0.f);
        *(float4*)(g_h1 + (size_t)(base + n) * HH + q * 4) = o;
    }
}

// edge pass 2: 128 edges/block (grid 12500), 16 thr/edge, float4 + red.v4.
// unroll 4 -> 4 independent h1 gathers in flight per warp (latency-bound fix).
__global__ __launch_bounds__(256) void k_edge2(const int*   __restrict__ ei,
                                               const float* __restrict__ eattr,
                                               const float* __restrict__ We2,
                                               const float* __restrict__ be2) {
    __shared__ float sea[128 * EA];
    __shared__ int   ss[128], sd[128];
    int tid = threadIdx.x;
    size_t base = (size_t)blockIdx.x * 128;
    for (int i = tid; i < 128 * EA; i += 256) sea[i] = eattr[base * EA + i];
    if (tid < 128)       ss[tid] = ei[base + tid];
    else                 sd[tid - 128] = ei[EE + base + (tid - 128)];
    int q = tid & 15, el = tid >> 4;
    ulonglong2 rw[EA];
#pragma unroll
    for (int a = 0; a < EA; a++) {
        float4 w = __ldg((const float4*)(We2 + a * HH + q * 4));
        rw[a].x = pack2f(w.x, w.y);
        rw[a].y = pack2f(w.z, w.w);
    }
    float4 rb = __ldg((const float4*)(be2 + q * 4));
    u64 rb0 = pack2f(rb.x, rb.y), rb1 = pack2f(rb.z, rb.w);
    __syncthreads();
#pragma unroll 4
    for (int sub = 0; sub < 8; sub++) {
        int e = sub * 16 + el;
        int s = ss[e], d = sd[e];
        float4 h = __ldg((const float4*)(g_h1 + (size_t)s * HH + q * 4));
        u64 v0 = rb0, v1 = rb1;
#pragma unroll
        for (int a = 0; a < EA; a++) {
            u64 ea2 = pack2(sea[e * EA + a]);
            v0 = fma2(rw[a].x, ea2, v0);
            v1 = fma2(rw[a].y, ea2, v1);
        }
        float2 lo = unpack2(v0), hi = unpack2(v1);
        float4 m;
        m.x = fmaxf(h.x + lo.x, 0.f);
        m.y = fmaxf(h.y + lo.y, 0.f);
        m.z = fmaxf(h.z + hi.x, 0.f);
        m.w = fmaxf(h.w + hi.y, 0.f);
        red4(g_agg2 + (size_t)d * HH + q * 4, m);
    }
}

// node MLP 2: 16 thr/group, 5 nodes/group, 80 nodes/block (grid 1250)
__global__ __launch_bounds__(256) void k_mlp2(const float* __restrict__ W21,
                                              const float* __restrict__ b21,
                                              const float* __restrict__ W22,
                                              const float* __restrict__ b22,
                                              const float* __restrict__ eps2) {
    __shared__ float sh[16][5][68];
    int tid = threadIdx.x;
    int q = tid & 15, nl = tid >> 4;
    int base = blockIdx.x * 80 + nl * 5;
    float epsv = 1.0f + __ldg(eps2);
#pragma unroll
    for (int n = 0; n < 5; n++) {
        size_t off = (size_t)(base + n) * HH + q * 4;
        float4 h1v = __ldg((const float4*)(g_h1 + off));
        float4 ag  = *(const float4*)(g_agg2 + off);
        float4 hin;
        hin.x = fmaf(epsv, h1v.x, ag.x);
        hin.y = fmaf(epsv, h1v.y, ag.y);
        hin.z = fmaf(epsv, h1v.z, ag.z);
        hin.w = fmaf(epsv, h1v.w, ag.w);
        *(float4*)&sh[nl][n][q * 4] = hin;
    }
    __syncwarp();
    u64 a0[5], a1[5];
    // ---- layer 1 ----
    {
        float4 bv = __ldg((const float4*)(b21 + q * 4));
#pragma unroll
        for (int n = 0; n < 5; n++) { a0[n] = pack2f(bv.x, bv.y); a1[n] = pack2f(bv.z, bv.w); }
#pragma unroll
        for (int j4 = 0; j4 < 16; j4++) {
            float4 w0 = __ldg((const float4*)(W21 + (j4 * 4 + 0) * HH + q * 4));
            float4 w1 = __ldg((const float4*)(W21 + (j4 * 4 + 1) * HH + q * 4));
            float4 w2 = __ldg((const float4*)(W21 + (j4 * 4 + 2) * HH + q * 4));
            float4 w3 = __ldg((const float4*)(W21 + (j4 * 4 + 3) * HH + q * 4));
#pragma unroll
            for (int n = 0; n < 5; n++) {
                float4 hv = *(const float4*)&sh[nl][n][j4 * 4];
                a0[n] = fma2(pack2f(w0.x, w0.y), pack2(hv.x), a0[n]);
                a1[n] = fma2(pack2f(w0.z, w0.w), pack2(hv.x), a1[n]);
                a0[n] = fma2(pack2f(w1.x, w1.y), pack2(hv.y), a0[n]);
                a1[n] = fma2(pack2f(w1.z, w1.w), pack2(hv.y), a1[n]);
                a0[n] = fma2(pack2f(w2.x, w2.y), pack2(hv.z), a0[n]);
                a1[n] = fma2(pack2f(w2.z, w2.w), pack2(hv.z), a1[n]);
                a0[n] = fma2(pack2f(w3.x, w3.y), pack2(hv.w), a0[n]);
                a1[n] = fma2(pack2f(w3.z, w3.w), pack2(hv.w), a1[n]);
            }
        }
        __syncwarp();
#pragma unroll
        for (int n = 0; n < 5; n++) {
            float2 lo = unpack2(a0[n]), hi = unpack2(a1[n]);
            float4 t;
            t.x = fmaxf(lo.x, 0.f); t.y = fmaxf(lo.y, 0.f);
            t.z = fmaxf(hi.x, 0.f); t.w = fmaxf(hi.y, 0.f);
            *(float4*)&sh[nl][n][q * 4] = t;
        }
        __syncwarp();
    }
    // ---- layer 2 ----
    {
        float4 bv = __ldg((const float4*)(b22 + q * 4));
#pragma unroll
        for (int n = 0; n < 5; n++) { a0[n] = pack2f(bv.x, bv.y); a1[n] = pack2f(bv.z, bv.w); }
#pragma unroll
        for (int j4 = 0; j4 < 16; j4++) {
            float4 w0 = __ldg((const float4*)(W22 + (j4 * 4 + 0) * HH + q * 4));
            float4 w1 = __ldg((const float4*)(W22 + (j4 * 4 + 1) * HH + q * 4));
            float4 w2 = __ldg((const float4*)(W22 + (j4 * 4 + 2) * HH + q * 4));
            float4 w3 = __ldg((const float4*)(W22 + (j4 * 4 + 3) * HH + q * 4));
#pragma unroll
            for (int n = 0; n < 5; n++) {
                float4 hv = *(const float4*)&sh[nl][n][j4 * 4];
                a0[n] = fma2(pack2f(w0.x, w0.y), pack2(hv.x), a0[n]);
                a1[n] = fma2(pack2f(w0.z, w0.w), pack2(hv.x), a1[n]);
                a0[n] = fma2(pack2f(w1.x, w1.y), pack2(hv.y), a0[n]);
                a1[n] = fma2(pack2f(w1.z, w1.w), pack2(hv.y), a1[n]);
                a0[n] = fma2(pack2f(w2.x, w2.y), pack2(hv.z), a0[n]);
                a1[n] = fma2(pack2f(w2.z, w2.w), pack2(hv.z), a1[n]);
                a0[n] = fma2(pack2f(w3.x, w3.y), pack2(hv.w), a0[n]);
                a1[n] = fma2(pack2f(w3.z, w3.w), pack2(hv.w), a1[n]);
            }
        }
#pragma unroll
        for (int n = 0; n < 5; n++) {
            float2 lo = unpack2(a0[n]), hi = unpack2(a1[n]);
            float4 o;
            o.x = fmaxf(lo.x, 0.f); o.y = fmaxf(lo.y, 0.f);
            o.z = fmaxf(hi.x, 0.f); o.w = fmaxf(hi.y, 0.f);
            *(float4*)(g_h2 + (size_t)(base + n) * HH + q * 4) = o;
        }
    }
}

// heads: 16 thr/group, 5 nodes/group; thread q owns latent dims 2q,2q+1.
// pooled sums run-length-accumulated (batch sorted, nodes consecutive per group).
__global__ __launch_bounds__(256) void k_heads(const float* __restrict__ Wmu,
                                               const float* __restrict__ bmu,
                                               const float* __restrict__ Wlv,
                                               const float* __restrict__ blv,
                                               const int*   __restrict__ batch,
                                               float* __restrict__ out) {
    __shared__ float sh[16][5][68];
    int tid = threadIdx.x;
    int q = tid & 15, nl = tid >> 4;
    int base = blockIdx.x * 80 + nl * 5;
    int l0 = q * 2;
#pragma unroll
    for (int n = 0; n < 5; n++) {
        float4 h = __ldg((const float4*)(g_h2 + (size_t)(base + n) * HH + q * 4));
        *(float4*)&sh[nl][n][q * 4] = h;
    }
    __syncwarp();
    u64 amu[5], alv[5];
    u64 bm = __ldg((const u64*)(bmu + l0));
    u64 bl = __ldg((const u64*)(blv + l0));
#pragma unroll
    for (int n = 0; n < 5; n++) { amu[n] = bm; alv[n] = bl; }
#pragma unroll
    for (int j4 = 0; j4 < 16; j4++) {
        u64 wm0 = __ldg((const u64*)(Wmu + (j4 * 4 + 0) * LL + l0));
        u64 wm1 = __ldg((const u64*)(Wmu + (j4 * 4 + 1) * LL + l0));
        u64 wm2 = __ldg((const u64*)(Wmu + (j4 * 4 + 2) * LL + l0));
        u64 wm3 = __ldg((const u64*)(Wmu + (j4 * 4 + 3) * LL + l0));
        u64 wl0 = __ldg((const u64*)(Wlv + (j4 * 4 + 0) * LL + l0));
        u64 wl1 = __ldg((const u64*)(Wlv + (j4 * 4 + 1) * LL + l0));
        u64 wl2 = __ldg((const u64*)(Wlv + (j4 * 4 + 2) * LL + l0));
        u64 wl3 = __ldg((const u64*)(Wlv + (j4 * 4 + 3) * LL + l0));
#pragma unroll
        for (int n = 0; n < 5; n++) {
            float4 hv = *(const float4*)&sh[nl][n][j4 * 4];
            u64 h0 = pack2(hv.x), h1 = pack2(hv.y), h2 = pack2(hv.z), h3 = pack2(hv.w);
            amu[n] = fma2(wm0, h0, amu[n]);
            alv[n] = fma2(wl0, h0, alv[n]);
            amu[n] = fma2(wm1, h1, amu[n]);
            alv[n] = fma2(wl1, h1, alv[n]);
            amu[n] = fma2(wm2, h2, amu[n]);
            alv[n] = fma2(wl2, h2, alv[n]);
            amu[n] = fma2(wm3, h3, amu[n]);
            alv[n] = fma2(wl3, h3, alv[n]);
        }
    }
    float* out_z  = out;
    float* out_mu = out + (size_t)NN * LL;
    float* out_lv = out + (size_t)2 * NN * LL;
    float2 accz = make_float2(0.f, 0.f);
    float accn = 0.f;
    int accb = -1;
#pragma unroll
    for (int n = 0; n < 5; n++) {
        int node = base + n;
        float2 mu = unpack2(amu[n]), lv = unpack2(alv[n]);
        uint32_t flat = (uint32_t)node * LL + (uint32_t)l0;
        float nz0 = jax_normal_42(flat);
        float nz1 = jax_normal_42(flat + 1u);
        float2 z;
        z.x = fmaf(nz0, expf(0.5f * lv.x), mu.x);
        z.y = fmaf(nz1, expf(0.5f * lv.y), mu.y);
        *(float2*)(out_z  + flat) = z;
        *(float2*)(out_mu + flat) = mu;
        *(float2*)(out_lv + flat) = lv;
        int b = __ldg(batch + node);
        if (b != accb) {
            if (accb >= 0) {
                red2(g_zsum + accb * LL + l0, accz);
                if (q == 0) atomicAdd(&g_cnt[accb], accn);
            }
            accb = b; accz = z; accn = 1.f;
        } else {
            accz.x += z.x; accz.y += z.y; accn += 1.f;
        }
    }
    if (accb >= 0) {
        red2(g_zsum + accb * LL + l0, accz);
        if (q == 0) atomicAdd(&g_cnt[accb], accn);
    }
}

__global__ __launch_bounds__(256) void k_logits(const float* __restrict__ Wc,
                                                const float* __restrict__ bc,
                                                float* __restrict__ out) {
    int g = blockIdx.x * 256 + threadIdx.x;
    if (g >= GG) return;
    float inv = 1.0f / fmaxf(g_cnt[g], 1.0f);
    float acc[CC];
#pragma unroll
    for (int c = 0; c < CC; c++) acc[c] = __ldg(bc + c);
#pragma unroll
    for (int l = 0; l < LL; l++) {
        float v = g_zsum[g * LL + l] * inv;
#pragma unroll
        for (int c = 0; c < CC; c++) acc[c] = fmaf(v, __ldg(Wc + l * CC + c), acc[c]);
    }
    float* out_lg = out + (size_t)3 * NN * LL;
#pragma unroll
    for (int c = 0; c < CC; c++) out_lg[(size_t)g * CC + c] = acc[c];
}

// ---------------- launch -----------------------------------------------------
extern "C" void kernel_launch(void* const* d_in, const int* in_sizes, int n_in,
                              void* d_out, int out_size) {
    const float* x     = (const float*)d_in[0];
    const int*   ei    = (const int*)  d_in[1];
    const float* eattr = (const float*)d_in[2];
    const int*   batch = (const int*)  d_in[3];
    const float* We1  = (const float*)d_in[4];
    const float* be1  = (const float*)d_in[5];
    const float* W11  = (const float*)d_in[6];
    const float* b11  = (const float*)d_in[7];
    const float* W12  = (const float*)d_in[8];
    const float* b12  = (const float*)d_in[9];
    const float* eps1 = (const float*)d_in[10];
    const float* We2  = (const float*)d_in[11];
    const float* be2  = (const float*)d_in[12];
    const float* W21  = (const float*)d_in[13];
    const float* b21  = (const float*)d_in[14];
    const float* W22  = (const float*)d_in[15];
    const float* b22  = (const float*)d_in[16];
    const float* eps2 = (const float*)d_in[17];
    const float* Wmu  = (const float*)d_in[18];
    const float* bmu  = (const float*)d_in[19];
    const float* Wlv  = (const float*)d_in[20];
    const float* blv  = (const float*)d_in[21];
    const float* Wc   = (const float*)d_in[22];
    const float* bc   = (const float*)d_in[23];
    float* out = (float*)d_out;

    k_zero  <<<98, 256>>>();
    k_edge1 <<<EE / 256, 256>>>(x, ei, eattr, We1, be1);
    k_mlp1  <<<NN / 80, 256>>>(x, W11, b11, W12, b12, eps1);
    k_edge2 <<<EE / 128, 256>>>(ei, eattr, We2, be2);
    k_mlp2  <<<NN / 80, 256>>>(W21, b21, W22, b22, eps2);
    k_heads <<<NN / 80, 256>>>(Wmu, bmu, Wlv, blv, batch, out);
    k_logits<<<2, 256>>>(Wc, bc, out);
}